// round 3
// baseline (speedup 1.0000x reference)
#include <cuda_runtime.h>
#include <math.h>

#define N_EDGES 3200000
#define N_SG    800000
#define T       256
#define EPB     (T * 4)                      // 1024 edges per chunk
#define CHUNKS  (N_EDGES / EPB)              // 3125
#define SG_CHUNKS ((N_SG + EPB - 1) / EPB)   // 782 (chunk 781 partial)

__device__ float g_partials[SG_CHUNKS];
__device__ unsigned g_cnt = 0;
__device__ unsigned g_release = 0;

// rule r = a*3+b
__constant__ float c_mat0[9] = {-0.2f, -0.1f, -0.05f, -0.05f, -0.05f, -0.01f, -0.055f, -0.01f, 0.0f};
__constant__ float c_mat1[9] = {0.0f, -0.002f, -0.001f, -0.001f, -0.001f, -0.0002f, 0.0008f, -0.0002f, 0.0f};
__constant__ float c_bias[9] = {1.0f, 0.7f, 0.275f, 0.4f, 0.25f, 0.07f, 0.2225f, 0.07f, 0.0f};

__device__ __forceinline__ float edge_attention(float4 fs, float4 fd) {
    float d0 = fd.x - fs.x;
    float d1 = fd.y - fs.y;
    float v0 = fd.z - fs.z;
    float v1 = fd.w - fs.w;

    float r2 = d0 * d0 + d1 * d1;
    float q2 = v0 * v0 + v1 * v1;
    float x1 = (r2 > 0.0f) ? r2 * __frsqrt_rn(r2) : 0.0f;
    float vn = (q2 > 0.0f) ? q2 * __frsqrt_rn(q2) : 0.0f;
    float cosv = __fdividef(d0 * v0 + d1 * v1, x1 * vn + 1e-8f);
    cosv = fminf(fmaxf(cosv, -1.0f + 1e-6f), 1.0f - 1e-6f);
    float x2 = acosf(cosv) * 57.29577951308232f;   // degrees

    const float k1 = 0.8888888888888889f;          // 1/(2*0.75^2)
    const float k2 = 5.555555555555556e-4f;        // 1/(2*30^2)
    float a1 = x1 - 2.0f, a2 = x1 - 4.0f;
    float b1 = x2 - 90.0f, b2 = x2 - 180.0f;
    float m1[3], m2[3];
    m1[0] = __expf(-x1 * x1 * k1);
    m1[1] = __expf(-a1 * a1 * k1);
    m1[2] = __expf(-a2 * a2 * k1);
    m2[0] = __expf(-x2 * x2 * k2);
    m2[1] = __expf(-b1 * b1 * k2);
    m2[2] = __expf(-b2 * b2 * k2);

    float num = 0.0f, den = 0.0f;
#pragma unroll
    for (int a = 0; a < 3; a++) {
#pragma unroll
        for (int b = 0; b < 3; b++) {
            int r = a * 3 + b;
            float tr = fminf(m1[a], m2[b]);
            float cons = fmaf(x1, c_mat0[r], fmaf(x2, c_mat1[r], c_bias[r]));
            num = fmaf(tr, cons, num);
            den += tr;
        }
    }
    return __fdividef(num, den);
}

__device__ __forceinline__ float block_reduce_sum(float v, float* smem) {
#pragma unroll
    for (int off = 16; off > 0; off >>= 1)
        v += __shfl_xor_sync(0xFFFFFFFFu, v, off);
    int wid = threadIdx.x >> 5;
    int lid = threadIdx.x & 31;
    if (lid == 0) smem[wid] = v;
    __syncthreads();
    if (wid == 0) {
        v = (lid < 8) ? smem[lid] : 0.0f;
#pragma unroll
        for (int off = 4; off > 0; off >>= 1)
            v += __shfl_xor_sync(0xFFFFFFFFu, v, off);
    }
    return v;  // valid in thread 0
}

__global__ void __launch_bounds__(T) fused_kernel(
        const float4* __restrict__ feat,
        const int4* __restrict__ src4,
        const int4* __restrict__ dst4,
        float* __restrict__ out) {
    __shared__ float smem[32];
    __shared__ float s_inv;

    // read release token BEFORE arriving (release fires only after ALL blocks
    // arrive, and every block reads before it arrives -> no missed wakeup)
    unsigned my_rel;
    if (threadIdx.x == 0) my_rel = *(volatile unsigned*)&g_release;

    float4* out4 = reinterpret_cast<float4*>(out);

    // ---------------- phase 1: attention (+ exp & partials in softmax region)
    for (int chunk = blockIdx.x; chunk < CHUNKS; chunk += gridDim.x) {
        int t = chunk * T + threadIdx.x;   // quad index
        int e0 = t * 4;

        int4 s4 = __ldg(&src4[t]);
        int4 d4 = __ldg(&dst4[t]);

        float4 fs0 = __ldg(&feat[s4.x]);
        float4 fd0 = __ldg(&feat[d4.x]);
        float4 fs1 = __ldg(&feat[s4.y]);
        float4 fd1 = __ldg(&feat[d4.y]);
        float4 fs2 = __ldg(&feat[s4.z]);
        float4 fd2 = __ldg(&feat[d4.z]);
        float4 fs3 = __ldg(&feat[s4.w]);
        float4 fd3 = __ldg(&feat[d4.w]);

        float4 att;
        att.x = edge_attention(fs0, fd0);
        att.y = edge_attention(fs1, fd1);
        att.z = edge_attention(fs2, fd2);
        att.w = edge_attention(fs3, fd3);

        if (chunk < SG_CHUNKS) {            // uniform across block
            float s = 0.0f;
            if (e0 + 0 < N_SG) { att.x = __expf(att.x); s += att.x; }
            if (e0 + 1 < N_SG) { att.y = __expf(att.y); s += att.y; }
            if (e0 + 2 < N_SG) { att.z = __expf(att.z); s += att.z; }
            if (e0 + 3 < N_SG) { att.w = __expf(att.w); s += att.w; }
            out4[t] = att;                  // softmax region holds exp(att)
            s = block_reduce_sum(s, smem);
            if (threadIdx.x == 0) g_partials[chunk] = s;
        } else {
            out4[t] = att;
        }
    }

    // ---------------- grid barrier (sense via monotonically increasing token)
    __threadfence();
    __syncthreads();
    if (threadIdx.x == 0) {
        unsigned ticket = atomicAdd(&g_cnt, 1);
        if (ticket == gridDim.x - 1) {
            g_cnt = 0;                       // reset for next graph replay
            __threadfence();
            atomicAdd(&g_release, 1);
        }
        while (*(volatile unsigned*)&g_release == my_rel) { __nanosleep(64); }
    }
    __syncthreads();
    __threadfence();

    // ---------------- total (redundant per block, fixed order: deterministic)
    {
        float v = 0.0f;
        for (int i = threadIdx.x; i < SG_CHUNKS; i += T)
            v += g_partials[i];
        v = block_reduce_sum(v, smem);
        if (threadIdx.x == 0) s_inv = __frcp_rn(v);
        __syncthreads();
    }
    float inv = s_inv;

    // ---------------- phase 2: scale softmax region (L2-hot, pure multiply)
    for (int chunk = blockIdx.x; chunk < SG_CHUNKS; chunk += gridDim.x) {
        int t = chunk * T + threadIdx.x;
        int e0 = t * 4;
        if (e0 + 3 < N_SG) {
            float4 a = out4[t];
            a.x *= inv; a.y *= inv; a.z *= inv; a.w *= inv;
            out4[t] = a;
        } else {
            for (int e = e0; e < N_SG; e++) out[e] *= inv;
        }
    }
}

extern "C" void kernel_launch(void* const* d_in, const int* in_sizes, int n_in,
                              void* d_out, int out_size) {
    const float4* feat = (const float4*)d_in[0];
    const int4* src4 = (const int4*)d_in[1];
    const int4* dst4 = (const int4*)d_in[2];
    float* out = (float*)d_out;

    static int grid = 0;
    if (grid == 0) {
        int dev = 0, sms = 0, bpm = 0;
        cudaGetDevice(&dev);
        cudaDeviceGetAttribute(&sms, cudaDevAttrMultiProcessorCount, dev);
        cudaOccupancyMaxActiveBlocksPerMultiprocessor(&bpm, fused_kernel, T, 0);
        grid = sms * bpm;
        if (grid > CHUNKS) grid = CHUNKS;
        if (grid < 1) grid = 1;
    }

    fused_kernel<<<grid, T>>>(feat, src4, dst4, out);
}

// round 4
// speedup vs baseline: 1.3795x; 1.3795x over previous
#include <cuda_runtime.h>
#include <math.h>

#define N_EDGES 3200000
#define N_SG    800000
#define T       256
#define EPT     2                               // edges per thread (attn)
#define EPB     (T * EPT)                       // 512 edges per block
#define ATT_B   (N_EDGES / EPB)                 // 6250
#define SG_B    ((N_SG + EPB - 1) / EPB)        // 1563 (block 1562 partial)

#define NORM_EPT 16                             // elems per thread (norm)
#define NORM_B  (N_SG / (T * NORM_EPT))         // 196 blocks, minus remainder
// 800000 / (256*16) = 195.3 -> use 196 with bounds check

__device__ float g_partials[SG_B];

// rule r = a*3+b
__constant__ float c_mat0[9] = {-0.2f, -0.1f, -0.05f, -0.05f, -0.05f, -0.01f, -0.055f, -0.01f, 0.0f};
__constant__ float c_mat1[9] = {0.0f, -0.002f, -0.001f, -0.001f, -0.001f, -0.0002f, 0.0008f, -0.0002f, 0.0f};
__constant__ float c_bias[9] = {1.0f, 0.7f, 0.275f, 0.4f, 0.25f, 0.07f, 0.2225f, 0.07f, 0.0f};

__device__ __forceinline__ float edge_attention(float4 fs, float4 fd) {
    float d0 = fd.x - fs.x;
    float d1 = fd.y - fs.y;
    float v0 = fd.z - fs.z;
    float v1 = fd.w - fs.w;

    float r2 = d0 * d0 + d1 * d1;
    float q2 = v0 * v0 + v1 * v1;
    float x1 = (r2 > 0.0f) ? r2 * __frsqrt_rn(r2) : 0.0f;
    float vn = (q2 > 0.0f) ? q2 * __frsqrt_rn(q2) : 0.0f;
    float cosv = __fdividef(d0 * v0 + d1 * v1, x1 * vn + 1e-8f);
    cosv = fminf(fmaxf(cosv, -1.0f + 1e-6f), 1.0f - 1e-6f);
    float x2 = acosf(cosv) * 57.29577951308232f;   // degrees

    const float k1 = 0.8888888888888889f;          // 1/(2*0.75^2)
    const float k2 = 5.555555555555556e-4f;        // 1/(2*30^2)
    float a1 = x1 - 2.0f, a2 = x1 - 4.0f;
    float b1 = x2 - 90.0f, b2 = x2 - 180.0f;
    float m1[3], m2[3];
    m1[0] = __expf(-x1 * x1 * k1);
    m1[1] = __expf(-a1 * a1 * k1);
    m1[2] = __expf(-a2 * a2 * k1);
    m2[0] = __expf(-x2 * x2 * k2);
    m2[1] = __expf(-b1 * b1 * k2);
    m2[2] = __expf(-b2 * b2 * k2);

    float num = 0.0f, den = 0.0f;
#pragma unroll
    for (int a = 0; a < 3; a++) {
#pragma unroll
        for (int b = 0; b < 3; b++) {
            int r = a * 3 + b;
            float tr = fminf(m1[a], m2[b]);
            float cons = fmaf(x1, c_mat0[r], fmaf(x2, c_mat1[r], c_bias[r]));
            num = fmaf(tr, cons, num);
            den += tr;
        }
    }
    return __fdividef(num, den);
}

__device__ __forceinline__ float block_reduce_sum(float v, float* smem) {
#pragma unroll
    for (int off = 16; off > 0; off >>= 1)
        v += __shfl_xor_sync(0xFFFFFFFFu, v, off);
    int wid = threadIdx.x >> 5;
    int lid = threadIdx.x & 31;
    if (lid == 0) smem[wid] = v;
    __syncthreads();
    if (wid == 0) {
        v = (lid < 8) ? smem[lid] : 0.0f;
#pragma unroll
        for (int off = 4; off > 0; off >>= 1)
            v += __shfl_xor_sync(0xFFFFFFFFu, v, off);
    }
    return v;  // valid in thread 0
}

// 2 edges/thread; softmax region stores exp(att) and block partial sums.
__global__ void __launch_bounds__(T, 6) attn_kernel(
        const float4* __restrict__ feat,
        const int2* __restrict__ src2,
        const int2* __restrict__ dst2,
        float* __restrict__ out) {
    int t = blockIdx.x * T + threadIdx.x;   // pair index
    int e0 = t * 2;

    int2 s2 = __ldg(&src2[t]);
    int2 d2 = __ldg(&dst2[t]);

    float4 fs0 = __ldg(&feat[s2.x]);
    float4 fd0 = __ldg(&feat[d2.x]);
    float4 fs1 = __ldg(&feat[s2.y]);
    float4 fd1 = __ldg(&feat[d2.y]);

    float2 att;
    att.x = edge_attention(fs0, fd0);
    att.y = edge_attention(fs1, fd1);

    if (blockIdx.x < SG_B) {
        __shared__ float smem[32];
        float s = 0.0f;
        // N_SG even, e0 even -> both edges in or out together
        if (e0 < N_SG) {
            att.x = __expf(att.x);
            att.y = __expf(att.y);
            s = att.x + att.y;
        }
        reinterpret_cast<float2*>(out)[t] = att;
        s = block_reduce_sum(s, smem);
        if (threadIdx.x == 0) g_partials[blockIdx.x] = s;
    } else {
        reinterpret_cast<float2*>(out)[t] = att;
    }
}

// pure scale over softmax region; partials reduced redundantly per block
__global__ void __launch_bounds__(T) norm_kernel(float* __restrict__ out) {
    __shared__ float smem[32];
    __shared__ float s_inv;
    float v = 0.0f;
    for (int i = threadIdx.x; i < SG_B; i += T)
        v += g_partials[i];
    v = block_reduce_sum(v, smem);
    if (threadIdx.x == 0) s_inv = __frcp_rn(v);
    __syncthreads();
    float inv = s_inv;

    float4* out4 = reinterpret_cast<float4*>(out);
    int base = (blockIdx.x * T + threadIdx.x) * (NORM_EPT / 4);
#pragma unroll
    for (int j = 0; j < NORM_EPT / 4; j++) {
        int q = base + j;
        if (q * 4 < N_SG) {
            float4 a = out4[q];
            a.x *= inv; a.y *= inv; a.z *= inv; a.w *= inv;
            out4[q] = a;
        }
    }
}

extern "C" void kernel_launch(void* const* d_in, const int* in_sizes, int n_in,
                              void* d_out, int out_size) {
    const float4* feat = (const float4*)d_in[0];
    const int2* src2 = (const int2*)d_in[1];
    const int2* dst2 = (const int2*)d_in[2];
    float* out = (float*)d_out;

    attn_kernel<<<ATT_B, T>>>(feat, src2, dst2, out);
    int norm_blocks = (N_SG + T * NORM_EPT - 1) / (T * NORM_EPT);  // 196
    norm_kernel<<<norm_blocks, T>>>(out);
}

// round 5
// speedup vs baseline: 1.3908x; 1.0082x over previous
#include <cuda_runtime.h>
#include <math.h>

#define N_EDGES 3200000
#define N_SG    800000
#define T       256
#define ATT_B   (N_EDGES / T)          // 12500 blocks, 1 edge/thread
#define SG_B    (N_SG / T)             // 3125 blocks cover the softmax region exactly

__device__ float g_partials[SG_B];
__device__ float g_inv;

// rule r = a*3+b
__constant__ float c_mat0[9] = {-0.2f, -0.1f, -0.05f, -0.05f, -0.05f, -0.01f, -0.055f, -0.01f, 0.0f};
__constant__ float c_mat1[9] = {0.0f, -0.002f, -0.001f, -0.001f, -0.001f, -0.0002f, 0.0008f, -0.0002f, 0.0f};
__constant__ float c_bias[9] = {1.0f, 0.7f, 0.275f, 0.4f, 0.25f, 0.07f, 0.2225f, 0.07f, 0.0f};

__device__ __forceinline__ float edge_attention(float4 fs, float4 fd) {
    float d0 = fd.x - fs.x;
    float d1 = fd.y - fs.y;
    float v0 = fd.z - fs.z;
    float v1 = fd.w - fs.w;

    float r2 = d0 * d0 + d1 * d1;
    float q2 = v0 * v0 + v1 * v1;
    float x1 = (r2 > 0.0f) ? r2 * __frsqrt_rn(r2) : 0.0f;
    float vn = (q2 > 0.0f) ? q2 * __frsqrt_rn(q2) : 0.0f;
    float cosv = __fdividef(d0 * v0 + d1 * v1, x1 * vn + 1e-8f);
    cosv = fminf(fmaxf(cosv, -1.0f + 1e-6f), 1.0f - 1e-6f);
    float x2 = acosf(cosv) * 57.29577951308232f;   // degrees

    const float k1 = 0.8888888888888889f;          // 1/(2*0.75^2)
    const float k2 = 5.555555555555556e-4f;        // 1/(2*30^2)
    float a1 = x1 - 2.0f, a2 = x1 - 4.0f;
    float b1 = x2 - 90.0f, b2 = x2 - 180.0f;
    float m1[3], m2[3];
    m1[0] = __expf(-x1 * x1 * k1);
    m1[1] = __expf(-a1 * a1 * k1);
    m1[2] = __expf(-a2 * a2 * k1);
    m2[0] = __expf(-x2 * x2 * k2);
    m2[1] = __expf(-b1 * b1 * k2);
    m2[2] = __expf(-b2 * b2 * k2);

    float num = 0.0f, den = 0.0f;
#pragma unroll
    for (int a = 0; a < 3; a++) {
#pragma unroll
        for (int b = 0; b < 3; b++) {
            int r = a * 3 + b;
            float tr = fminf(m1[a], m2[b]);
            float cons = fmaf(x1, c_mat0[r], fmaf(x2, c_mat1[r], c_bias[r]));
            num = fmaf(tr, cons, num);
            den += tr;
        }
    }
    return __fdividef(num, den);
}

__device__ __forceinline__ float block_reduce_sum_256(float v, float* smem) {
#pragma unroll
    for (int off = 16; off > 0; off >>= 1)
        v += __shfl_xor_sync(0xFFFFFFFFu, v, off);
    int wid = threadIdx.x >> 5;
    int lid = threadIdx.x & 31;
    if (lid == 0) smem[wid] = v;
    __syncthreads();
    if (wid == 0) {
        v = (lid < 8) ? smem[lid] : 0.0f;
#pragma unroll
        for (int off = 4; off > 0; off >>= 1)
            v += __shfl_xor_sync(0xFFFFFFFFu, v, off);
    }
    return v;  // valid in thread 0
}

// 1 edge/thread, high occupancy; softmax region stores exp(att) + block partial
__global__ void __launch_bounds__(T, 6) attn_kernel(
        const float4* __restrict__ feat,
        const int* __restrict__ src,
        const int* __restrict__ dst,
        float* __restrict__ out) {
    int e = blockIdx.x * T + threadIdx.x;

    int s = __ldg(&src[e]);
    int t = __ldg(&dst[e]);
    float4 fs = __ldg(&feat[s]);
    float4 fd = __ldg(&feat[t]);

    float att = edge_attention(fs, fd);

    if (blockIdx.x < SG_B) {            // whole block inside softmax region
        __shared__ float smem[8];
        att = __expf(att);
        out[e] = att;                   // region holds exp(att)
        float sum = block_reduce_sum_256(att, smem);
        if (threadIdx.x == 0) g_partials[blockIdx.x] = sum;
    } else {
        out[e] = att;
    }
}

// single block reduces all partials -> scalar 1/sum
__global__ void __launch_bounds__(1024) finalize_kernel() {
    __shared__ float smem[32];
    float v = 0.0f;
    for (int i = threadIdx.x; i < SG_B; i += 1024)
        v += g_partials[i];
#pragma unroll
    for (int off = 16; off > 0; off >>= 1)
        v += __shfl_xor_sync(0xFFFFFFFFu, v, off);
    int wid = threadIdx.x >> 5;
    int lid = threadIdx.x & 31;
    if (lid == 0) smem[wid] = v;
    __syncthreads();
    if (wid == 0) {
        v = smem[lid];
#pragma unroll
        for (int off = 16; off > 0; off >>= 1)
            v += __shfl_xor_sync(0xFFFFFFFFu, v, off);
        if (lid == 0) g_inv = __frcp_rn(v);
    }
}

// pure float4 scale by the precomputed scalar; prologue = 1 broadcast load
__global__ void __launch_bounds__(T) norm_kernel(float* __restrict__ out) {
    float inv = g_inv;                  // L2-broadcast scalar
    int q = blockIdx.x * T + threadIdx.x;   // quad index; N_SG % 1024 == 0... (800000/4=200000)
    if (q < N_SG / 4) {
        float4* out4 = reinterpret_cast<float4*>(out);
        float4 a = out4[q];
        a.x *= inv; a.y *= inv; a.z *= inv; a.w *= inv;
        out4[q] = a;
    }
}

extern "C" void kernel_launch(void* const* d_in, const int* in_sizes, int n_in,
                              void* d_out, int out_size) {
    const float4* feat = (const float4*)d_in[0];
    const int* src = (const int*)d_in[1];
    const int* dst = (const int*)d_in[2];
    float* out = (float*)d_out;

    attn_kernel<<<ATT_B, T>>>(feat, src, dst, out);
    finalize_kernel<<<1, 1024>>>();
    norm_kernel<<<(N_SG / 4 + T - 1) / T, T>>>(out);   // 782 blocks
}

// round 6
// speedup vs baseline: 1.4086x; 1.0129x over previous
#include <cuda_runtime.h>
#include <math.h>

#define N_EDGES 3200000
#define N_SG    800000
#define T       256
#define ATT_B   (N_EDGES / T)          // 12500 blocks, 1 edge/thread
#define SG_B    (N_SG / T)             // 3125 blocks cover softmax region exactly

__device__ float g_partials[SG_B];
__device__ float g_inv;

// rule r = a*3+b
__constant__ float c_mat0[9] = {-0.2f, -0.1f, -0.05f, -0.05f, -0.05f, -0.01f, -0.055f, -0.01f, 0.0f};
__constant__ float c_mat1[9] = {0.0f, -0.002f, -0.001f, -0.001f, -0.001f, -0.0002f, 0.0008f, -0.0002f, 0.0f};
__constant__ float c_bias[9] = {1.0f, 0.7f, 0.275f, 0.4f, 0.25f, 0.07f, 0.2225f, 0.07f, 0.0f};

__device__ __forceinline__ float edge_attention(float4 fs, float4 fd) {
    float d0 = fd.x - fs.x;
    float d1 = fd.y - fs.y;
    float v0 = fd.z - fs.z;
    float v1 = fd.w - fs.w;

    float r2 = d0 * d0 + d1 * d1;
    float q2 = v0 * v0 + v1 * v1;
    float x1 = (r2 > 0.0f) ? r2 * rsqrtf(r2) : 0.0f;
    float vn = (q2 > 0.0f) ? q2 * rsqrtf(q2) : 0.0f;
    float cosv = __fdividef(d0 * v0 + d1 * v1, x1 * vn + 1e-8f);
    cosv = fminf(fmaxf(cosv, -1.0f + 1e-6f), 1.0f - 1e-6f);

    // acos via minimax poly: acos(|x|) = sqrt(1-|x|) * p(|x|), then reflect.
    float ax = fabsf(cosv);
    float p = -0.0012624911f;
    p = fmaf(p, ax, 0.0066700901f);
    p = fmaf(p, ax, -0.0170881256f);
    p = fmaf(p, ax, 0.0308918810f);
    p = fmaf(p, ax, -0.0501743046f);
    p = fmaf(p, ax, 0.0889789874f);
    p = fmaf(p, ax, -0.2145988016f);
    p = fmaf(p, ax, 1.5707963050f);
    float u = 1.0f - ax;                 // >= 1e-6 after clamp
    float sq = u * rsqrtf(u);            // sqrt(1-|x|)
    float r = sq * p;                    // acos(|x|), [0, pi/2]
    float ang = (cosv >= 0.0f) ? r : (3.14159265358979f - r);
    float x2 = ang * 57.29577951308232f; // degrees

    // memberships as exp2(c1*x^2 + c2*x + c3) -- shared square, 1 EX2 each
    // k1 = 1/(2*0.75^2); c1 = -k1*log2(e) = -1.28239556
    // k2 = 1/(2*30^2);   c2 = -k2*log2(e) = -8.0149724e-4
    float w1 = x1 * x1;
    float w2 = x2 * x2;
    float a0 = -1.28239556f * w1;
    float b0 = -8.0149724e-4f * w2;
    float m1[3], m2[3];
    m1[0] = exp2f(a0);
    m1[1] = exp2f(fmaf(5.12958224f, x1, a0 - 5.12958224f));    // center 2
    m1[2] = exp2f(fmaf(10.2591645f, x1, a0 - 20.5183290f));    // center 4
    m2[0] = exp2f(b0);
    m2[1] = exp2f(fmaf(0.144269504f, x2, b0 - 6.49212767f));   // center 90
    m2[2] = exp2f(fmaf(0.288539008f, x2, b0 - 25.9685107f));   // center 180

    float num = 0.0f, den = 0.0f;
#pragma unroll
    for (int a = 0; a < 3; a++) {
#pragma unroll
        for (int b = 0; b < 3; b++) {
            int rr = a * 3 + b;
            float tr = fminf(m1[a], m2[b]);
            float cons = fmaf(x1, c_mat0[rr], fmaf(x2, c_mat1[rr], c_bias[rr]));
            num = fmaf(tr, cons, num);
            den += tr;
        }
    }
    return __fdividef(num, den);
}

__device__ __forceinline__ float block_reduce_sum_256(float v, float* smem) {
#pragma unroll
    for (int off = 16; off > 0; off >>= 1)
        v += __shfl_xor_sync(0xFFFFFFFFu, v, off);
    int wid = threadIdx.x >> 5;
    int lid = threadIdx.x & 31;
    if (lid == 0) smem[wid] = v;
    __syncthreads();
    if (wid == 0) {
        v = (lid < 8) ? smem[lid] : 0.0f;
#pragma unroll
        for (int off = 4; off > 0; off >>= 1)
            v += __shfl_xor_sync(0xFFFFFFFFu, v, off);
    }
    return v;  // valid in thread 0
}

__global__ void __launch_bounds__(T, 6) attn_kernel(
        const float4* __restrict__ feat,
        const int* __restrict__ src,
        const int* __restrict__ dst,
        float* __restrict__ out) {
    int e = blockIdx.x * T + threadIdx.x;

    int s = __ldg(&src[e]);
    int t = __ldg(&dst[e]);
    float4 fs = __ldg(&feat[s]);
    float4 fd = __ldg(&feat[t]);

    float att = edge_attention(fs, fd);

    if (blockIdx.x < SG_B) {            // whole block inside softmax region
        __shared__ float smem[8];
        att = __expf(att);
        out[e] = att;                   // region holds exp(att)
        float sum = block_reduce_sum_256(att, smem);
        if (threadIdx.x == 0) g_partials[blockIdx.x] = sum;
    } else {
        out[e] = att;
    }
}

__global__ void __launch_bounds__(1024) finalize_kernel() {
    __shared__ float smem[32];
    float v = 0.0f;
    for (int i = threadIdx.x; i < SG_B; i += 1024)
        v += g_partials[i];
#pragma unroll
    for (int off = 16; off > 0; off >>= 1)
        v += __shfl_xor_sync(0xFFFFFFFFu, v, off);
    int wid = threadIdx.x >> 5;
    int lid = threadIdx.x & 31;
    if (lid == 0) smem[wid] = v;
    __syncthreads();
    if (wid == 0) {
        v = smem[lid];
#pragma unroll
        for (int off = 16; off > 0; off >>= 1)
            v += __shfl_xor_sync(0xFFFFFFFFu, v, off);
        if (lid == 0) g_inv = __frcp_rn(v);
    }
}

__global__ void __launch_bounds__(T) norm_kernel(float* __restrict__ out) {
    float inv = g_inv;                  // L2-broadcast scalar
    int q = blockIdx.x * T + threadIdx.x;
    if (q < N_SG / 4) {
        float4* out4 = reinterpret_cast<float4*>(out);
        float4 a = out4[q];
        a.x *= inv; a.y *= inv; a.z *= inv; a.w *= inv;
        out4[q] = a;
    }
}

extern "C" void kernel_launch(void* const* d_in, const int* in_sizes, int n_in,
                              void* d_out, int out_size) {
    const float4* feat = (const float4*)d_in[0];
    const int* src = (const int*)d_in[1];
    const int* dst = (const int*)d_in[2];
    float* out = (float*)d_out;

    attn_kernel<<<ATT_B, T>>>(feat, src, dst, out);
    finalize_kernel<<<1, 1024>>>();
    norm_kernel<<<(N_SG / 4 + T - 1) / T, T>>>(out);   // 782 blocks
}

// round 7
// speedup vs baseline: 1.4750x; 1.0471x over previous
#include <cuda_runtime.h>
#include <math.h>

#define N_EDGES 3200000
#define N_SG    800000
#define T       256
#define EPT     2                       // edges per thread
#define EPB     (T * EPT)               // 512
#define ATT_B   (N_EDGES / EPB)         // 6250
#define SG_B    (N_SG / EPB)            // 1562.5 -> region ends mid-block 1562
#define SG_BLK  ((N_SG + EPB - 1) / EPB) // 1563 blocks write partials

__device__ float g_partials[SG_BLK];
__device__ float g_inv;

// rule r = a*3+b
__constant__ float c_mat0[9] = {-0.2f, -0.1f, -0.05f, -0.05f, -0.05f, -0.01f, -0.055f, -0.01f, 0.0f};
__constant__ float c_mat1[9] = {0.0f, -0.002f, -0.001f, -0.001f, -0.001f, -0.0002f, 0.0008f, -0.0002f, 0.0f};
__constant__ float c_bias[9] = {1.0f, 0.7f, 0.275f, 0.4f, 0.25f, 0.07f, 0.2225f, 0.07f, 0.0f};

__device__ __forceinline__ float edge_attention(float4 fs, float4 fd) {
    float d0 = fd.x - fs.x;
    float d1 = fd.y - fs.y;
    float v0 = fd.z - fs.z;
    float v1 = fd.w - fs.w;

    float r2 = d0 * d0 + d1 * d1;
    float q2 = v0 * v0 + v1 * v1;
    float x1 = (r2 > 0.0f) ? r2 * rsqrtf(r2) : 0.0f;
    float vn = (q2 > 0.0f) ? q2 * rsqrtf(q2) : 0.0f;
    float cosv = __fdividef(d0 * v0 + d1 * v1, x1 * vn + 1e-8f);
    cosv = fminf(fmaxf(cosv, -1.0f + 1e-6f), 1.0f - 1e-6f);

    // acos(|x|) = sqrt(1-|x|) * p(|x|), reflect for x<0
    float ax = fabsf(cosv);
    float p = -0.0012624911f;
    p = fmaf(p, ax, 0.0066700901f);
    p = fmaf(p, ax, -0.0170881256f);
    p = fmaf(p, ax, 0.0308918810f);
    p = fmaf(p, ax, -0.0501743046f);
    p = fmaf(p, ax, 0.0889789874f);
    p = fmaf(p, ax, -0.2145988016f);
    p = fmaf(p, ax, 1.5707963050f);
    float u = 1.0f - ax;                 // >= 1e-6 after clamp
    float sq = u * rsqrtf(u);            // sqrt(1-|x|)
    float r = sq * p;                    // acos(|x|) in [0, pi/2]
    float ang = (cosv >= 0.0f) ? r : (3.14159265358979f - r);
    float x2 = ang * 57.29577951308232f; // degrees

    // memberships as exp2(quadratic) -- shared square, 1 EX2 each
    float w1 = x1 * x1;
    float w2 = x2 * x2;
    float a0 = -1.28239556f * w1;
    float b0 = -8.0149724e-4f * w2;
    float m1[3], m2[3];
    m1[0] = exp2f(a0);
    m1[1] = exp2f(fmaf(5.12958224f, x1, a0 - 5.12958224f));    // center 2
    m1[2] = exp2f(fmaf(10.2591645f, x1, a0 - 20.5183290f));    // center 4
    m2[0] = exp2f(b0);
    m2[1] = exp2f(fmaf(0.144269504f, x2, b0 - 6.49212767f));   // center 90
    m2[2] = exp2f(fmaf(0.288539008f, x2, b0 - 25.9685107f));   // center 180

    float num = 0.0f, den = 0.0f;
#pragma unroll
    for (int a = 0; a < 3; a++) {
#pragma unroll
        for (int b = 0; b < 3; b++) {
            int rr = a * 3 + b;
            float tr = fminf(m1[a], m2[b]);
            float cons = fmaf(x1, c_mat0[rr], fmaf(x2, c_mat1[rr], c_bias[rr]));
            num = fmaf(tr, cons, num);
            den += tr;
        }
    }
    return __fdividef(num, den);
}

__device__ __forceinline__ float block_reduce_sum_256(float v, float* smem) {
#pragma unroll
    for (int off = 16; off > 0; off >>= 1)
        v += __shfl_xor_sync(0xFFFFFFFFu, v, off);
    int wid = threadIdx.x >> 5;
    int lid = threadIdx.x & 31;
    if (lid == 0) smem[wid] = v;
    __syncthreads();
    if (wid == 0) {
        v = (lid < 8) ? smem[lid] : 0.0f;
#pragma unroll
        for (int off = 4; off > 0; off >>= 1)
            v += __shfl_xor_sync(0xFFFFFFFFu, v, off);
    }
    return v;  // valid in thread 0
}

// 2 edges/thread: 4 gathers in flight per thread, diet math
__global__ void __launch_bounds__(T, 6) attn_kernel(
        const float4* __restrict__ feat,
        const int2* __restrict__ src2,
        const int2* __restrict__ dst2,
        float* __restrict__ out) {
    int t = blockIdx.x * T + threadIdx.x;   // pair index
    int e0 = t * 2;

    int2 s2 = __ldg(&src2[t]);
    int2 d2 = __ldg(&dst2[t]);

    float4 fs0 = __ldg(&feat[s2.x]);
    float4 fd0 = __ldg(&feat[d2.x]);
    float4 fs1 = __ldg(&feat[s2.y]);
    float4 fd1 = __ldg(&feat[d2.y]);

    float2 att;
    att.x = edge_attention(fs0, fd0);
    att.y = edge_attention(fs1, fd1);

    if (blockIdx.x < SG_BLK) {
        __shared__ float smem[8];
        float s = 0.0f;
        // N_SG even, e0 even: both edges in or out of the region together
        if (e0 < N_SG) {
            att.x = __expf(att.x);
            att.y = __expf(att.y);
            s = att.x + att.y;
        }
        reinterpret_cast<float2*>(out)[t] = att;
        s = block_reduce_sum_256(s, smem);
        if (threadIdx.x == 0) g_partials[blockIdx.x] = s;
    } else {
        reinterpret_cast<float2*>(out)[t] = att;
    }
}

__global__ void __launch_bounds__(1024) finalize_kernel() {
    __shared__ float smem[32];
    float v = 0.0f;
    for (int i = threadIdx.x; i < SG_BLK; i += 1024)
        v += g_partials[i];
#pragma unroll
    for (int off = 16; off > 0; off >>= 1)
        v += __shfl_xor_sync(0xFFFFFFFFu, v, off);
    int wid = threadIdx.x >> 5;
    int lid = threadIdx.x & 31;
    if (lid == 0) smem[wid] = v;
    __syncthreads();
    if (wid == 0) {
        v = smem[lid];
#pragma unroll
        for (int off = 16; off > 0; off >>= 1)
            v += __shfl_xor_sync(0xFFFFFFFFu, v, off);
        if (lid == 0) g_inv = __frcp_rn(v);
    }
}

__global__ void __launch_bounds__(T) norm_kernel(float* __restrict__ out) {
    float inv = g_inv;                  // L2-broadcast scalar, trivial prologue
    int q = blockIdx.x * T + threadIdx.x;
    if (q < N_SG / 4) {
        float4* out4 = reinterpret_cast<float4*>(out);
        float4 a = out4[q];
        a.x *= inv; a.y *= inv; a.z *= inv; a.w *= inv;
        out4[q] = a;
    }
}

extern "C" void kernel_launch(void* const* d_in, const int* in_sizes, int n_in,
                              void* d_out, int out_size) {
    const float4* feat = (const float4*)d_in[0];
    const int2* src2 = (const int2*)d_in[1];
    const int2* dst2 = (const int2*)d_in[2];
    float* out = (float*)d_out;

    attn_kernel<<<ATT_B, T>>>(feat, src2, dst2, out);
    finalize_kernel<<<1, 1024>>>();
    norm_kernel<<<(N_SG / 4 + T - 1) / T, T>>>(out);   // 782 blocks
}